// round 2
// baseline (speedup 1.0000x reference)
#include <cuda_runtime.h>
#include <cuda_fp16.h>

#define BB   256
#define TT   512
#define HH   128
#define G4   512
#define IND  10
#define TRG  32

// ---------------- device-global scratch (no runtime allocation) ----------------
__device__ __half g_whh0h[G4 * HH];               // layer0 w_hh, fp16, k-blocked
__device__ __half g_whh1h[G4 * HH];               // layer1 w_hh, fp16, k-blocked
__device__ __half g_wih1h[G4 * HH];               // layer1 w_ih, fp16, k-blocked
__device__ float  g_h1[(size_t)BB * TT * HH];     // layer0 hidden sequence
__device__ float  g_xg1[(size_t)BB * TT * G4];    // layer1 input-gate preacts
__device__ float  g_h2last[BB * HH];              // final hidden state

// Blocked fp16 layout: dst_half[(k>>3)*4096 + g*8 + (k&7)] = w[g*128 + k].
// A warp of 32 consecutive gate-threads loading uint4 (8 halves) then reads
// 512 contiguous smem bytes -> conflict-free LDS.128.
__global__ void prep_kernel(const float* __restrict__ w_hh0,
                            const float* __restrict__ w_hh1,
                            const float* __restrict__ w_ih1)
{
    int idx = blockIdx.x * blockDim.x + threadIdx.x;
    if (idx >= 3 * G4 * HH) return;
    int m = idx >> 16;          // which matrix
    int e = idx & 65535;        // element within [512,128]
    int g = e >> 7;
    int k = e & 127;
    int dst = ((k >> 3) << 12) + (g << 3) + (k & 7);
    const float* s = (m == 0) ? w_hh0 : (m == 1 ? w_hh1 : w_ih1);
    __half*      d = (m == 0) ? g_whh0h : (m == 1 ? g_whh1h : g_wih1h);
    d[dst] = __float2half(s[e]);
}

__device__ __forceinline__ float sigf(float x) {
    return 1.0f / (1.0f + __expf(-x));
}
__device__ __forceinline__ float tanhfast(float x) {
    return 2.0f / (1.0f + __expf(-2.0f * x)) - 1.0f;
}

// ---------------- LSTM recurrence ----------------
// 128 CTAs x 2 batch rows, 512 threads; thread g computes gate g for both rows.
// smem layout (bytes):
//   [0,131072)            w_hh fp16 blocked
//   [131072,151552)       w_ih0 fp32, k-major [10][512]   (layer0 only)
//   [151552,153600)       bias  [512]                      (layer0 only)
//   [153600,154624)       hs    [2][128]  hidden state
//   [154624,158720)       gs    [2][512]  gate preacts
//   [158720,158848)       xs    [2][16]   current x       (layer0 only)
#define LSTM_SMEM 158848

template<int LAYER>
__global__ void __launch_bounds__(512, 1) lstm_layer_kernel(
    const float* __restrict__ x,
    const float* __restrict__ w_ih,
    const float* __restrict__ b_ih,
    const float* __restrict__ b_hh)
{
    extern __shared__ char smem[];
    __half* wsm    = (__half*)smem;
    float*  wih_s  = (float*)(smem + 131072);
    float*  bias_s = (float*)(smem + 151552);
    float*  hs     = (float*)(smem + 153600);
    float*  gs     = (float*)(smem + 154624);
    float*  xs     = (float*)(smem + 158720);

    const int tid = threadIdx.x;
    const int bb  = blockIdx.x;

    // load recurrent weights into smem (already blocked fp16)
    uint4*       wsm4 = (uint4*)wsm;
    const uint4* gw4  = (const uint4*)((LAYER == 0) ? g_whh0h : g_whh1h);
    #pragma unroll
    for (int i = 0; i < 16; i++)
        wsm4[i * 512 + tid] = gw4[i * 512 + tid];

    if (LAYER == 0) {
        for (int i = tid; i < G4 * IND; i += 512) {
            int g = i / IND, j = i - g * IND;
            wih_s[j * 512 + g] = w_ih[i];
        }
        bias_s[tid] = b_ih[tid] + b_hh[tid];
    }
    if (tid < 256) hs[tid] = 0.0f;

    float creg = 0.0f;                  // cell state, owned by threads < 256
    const int r_act = tid >> 7;
    const int j_act = tid & 127;

    // prefetch t=0 step inputs
    float xg0 = 0.0f, xg1v = 0.0f;
    int xr = 0, xj = 0;
    if (LAYER == 0) {
        if (tid < 2 * IND) {
            xr = tid / IND; xj = tid - xr * IND;
            xs[xr * 16 + xj] = x[(size_t)(2 * bb + xr) * (TT * IND) + xj];
        }
    } else {
        xg0  = g_xg1[((size_t)(2 * bb + 0) * TT + 0) * G4 + tid];
        xg1v = g_xg1[((size_t)(2 * bb + 1) * TT + 0) * G4 + tid];
    }
    __syncthreads();

    const float4* h0v = (const float4*)hs;
    const float4* h1v = (const float4*)(hs + 128);

    for (int t = 0; t < TT; t++) {
        // [A] prefetch next step's per-step inputs (hidden behind matmul)
        float nx = 0.0f, nxg0 = 0.0f, nxg1 = 0.0f;
        if (LAYER == 0) {
            if (tid < 2 * IND && t + 1 < TT)
                nx = x[(size_t)(2 * bb + xr) * (TT * IND) + (size_t)(t + 1) * IND + xj];
        } else {
            if (t + 1 < TT) {
                nxg0 = g_xg1[((size_t)(2 * bb + 0) * TT + (t + 1)) * G4 + tid];
                nxg1 = g_xg1[((size_t)(2 * bb + 1) * TT + (t + 1)) * G4 + tid];
            }
        }

        // [B] gate preactivations for gate tid, batch rows 0 and 1
        float a0p, a1p, a0q = 0.0f, a1q = 0.0f;
        if (LAYER == 0) {
            float bv = bias_s[tid];
            a0p = bv; a1p = bv;
            #pragma unroll
            for (int j = 0; j < IND; j++) {
                float wv = wih_s[j * 512 + tid];
                a0p = fmaf(xs[j],      wv, a0p);
                a1p = fmaf(xs[16 + j], wv, a1p);
            }
        } else {
            a0p = xg0; a1p = xg1v;
        }
        #pragma unroll
        for (int c = 0; c < 16; c++) {
            uint4 wp = wsm4[c * 512 + tid];
            float2 wA = __half22float2(*(__half2*)&wp.x);
            float2 wB = __half22float2(*(__half2*)&wp.y);
            float2 wC = __half22float2(*(__half2*)&wp.z);
            float2 wD = __half22float2(*(__half2*)&wp.w);
            float4 ha = h0v[c * 2], hb = h0v[c * 2 + 1];   // broadcast reads
            float4 ka = h1v[c * 2], kb = h1v[c * 2 + 1];
            a0p = fmaf(ha.x, wA.x, a0p); a0q = fmaf(ha.y, wA.y, a0q);
            a0p = fmaf(ha.z, wB.x, a0p); a0q = fmaf(ha.w, wB.y, a0q);
            a0p = fmaf(hb.x, wC.x, a0p); a0q = fmaf(hb.y, wC.y, a0q);
            a0p = fmaf(hb.z, wD.x, a0p); a0q = fmaf(hb.w, wD.y, a0q);
            a1p = fmaf(ka.x, wA.x, a1p); a1q = fmaf(ka.y, wA.y, a1q);
            a1p = fmaf(ka.z, wB.x, a1p); a1q = fmaf(ka.w, wB.y, a1q);
            a1p = fmaf(kb.x, wC.x, a1p); a1q = fmaf(kb.y, wC.y, a1q);
            a1p = fmaf(kb.z, wD.x, a1p); a1q = fmaf(kb.w, wD.y, a1q);
        }
        gs[tid]       = a0p + a0q;
        gs[512 + tid] = a1p + a1q;
        __syncthreads();

        // [C] activations + state update (threads < 256; one (row,unit) each)
        if (tid < 256) {
            const float* gr = gs + r_act * 512;
            float iv = sigf(gr[j_act]);
            float fv = sigf(gr[128 + j_act]);
            float gv = tanhfast(gr[256 + j_act]);
            float ov = sigf(gr[384 + j_act]);
            creg = fv * creg + iv * gv;
            float hn = ov * tanhfast(creg);
            hs[r_act * 128 + j_act] = hn;
            if (LAYER == 0) {
                g_h1[((size_t)(2 * bb + r_act) * TT + t) * HH + j_act] = hn;
            } else if (t == TT - 1) {
                g_h2last[(2 * bb + r_act) * HH + j_act] = hn;
            }
        }
        if (LAYER == 0) {
            if (tid < 2 * IND) xs[xr * 16 + xj] = nx;
        } else {
            xg0 = nxg0; xg1v = nxg1;
        }
        __syncthreads();
    }
}

// ---------------- layer-1 input projection GEMM ----------------
// xg1[bt, g] = h1[bt, :] . w_ih1[g, :] + b_ih1[g] + b_hh1[g]
// M = 131072, N = 512, K = 128. 512 threads (thread = gate), TRG=32 rows/CTA.
#define XG_SMEM (131072 + TRG * HH * 4)

__global__ void __launch_bounds__(512, 1) xgate1_kernel(
    const float* __restrict__ b_ih1, const float* __restrict__ b_hh1)
{
    extern __shared__ char smem[];
    __half* wsm = (__half*)smem;
    float*  h_s = (float*)(smem + 131072);

    const int tid = threadIdx.x;

    uint4*       wsm4 = (uint4*)wsm;
    const uint4* gw4  = (const uint4*)g_wih1h;
    #pragma unroll
    for (int i = 0; i < 16; i++)
        wsm4[i * 512 + tid] = gw4[i * 512 + tid];

    const size_t base = (size_t)blockIdx.x * TRG * HH;
    float4*       h_s4 = (float4*)h_s;
    const float4* src4 = (const float4*)(g_h1 + base);
    #pragma unroll
    for (int i = 0; i < (TRG * HH / 4) / 512; i++)
        h_s4[i * 512 + tid] = src4[i * 512 + tid];
    __syncthreads();

    float bv = b_ih1[tid] + b_hh1[tid];
    float acc[TRG];
    #pragma unroll
    for (int r = 0; r < TRG; r++) acc[r] = bv;

    #pragma unroll 1
    for (int c = 0; c < 16; c++) {
        uint4 wp = wsm4[c * 512 + tid];
        float2 wA = __half22float2(*(__half2*)&wp.x);
        float2 wB = __half22float2(*(__half2*)&wp.y);
        float2 wC = __half22float2(*(__half2*)&wp.z);
        float2 wD = __half22float2(*(__half2*)&wp.w);
        #pragma unroll
        for (int r = 0; r < TRG; r++) {
            float4 ha = *(const float4*)(h_s + r * HH + c * 8);
            float4 hb = *(const float4*)(h_s + r * HH + c * 8 + 4);
            float p = acc[r], q = 0.0f;
            p = fmaf(ha.x, wA.x, p); q = fmaf(ha.y, wA.y, q);
            p = fmaf(ha.z, wB.x, p); q = fmaf(ha.w, wB.y, q);
            p = fmaf(hb.x, wC.x, p); q = fmaf(hb.y, wC.y, q);
            p = fmaf(hb.z, wD.x, p); q = fmaf(hb.w, wD.y, q);
            acc[r] = p + q;
        }
    }

    #pragma unroll
    for (int r = 0; r < TRG; r++)
        g_xg1[((size_t)blockIdx.x * TRG + r) * G4 + tid] = acc[r];
}

// ---------------- final FC ----------------
__global__ void fc_kernel(const float* __restrict__ fc_w,
                          const float* __restrict__ fc_b,
                          float* __restrict__ out)
{
    int b = threadIdx.x;   // 256 threads
    const float* hrow = g_h2last + b * HH;
    #pragma unroll
    for (int c = 0; c < 10; c++) {
        float acc = fc_b[c];
        #pragma unroll
        for (int k = 0; k < HH; k++)
            acc = fmaf(hrow[k], fc_w[c * HH + k], acc);
        out[b * 10 + c] = acc;
    }
}

extern "C" void kernel_launch(void* const* d_in, const int* in_sizes, int n_in,
                              void* d_out, int out_size)
{
    const float* x     = (const float*)d_in[0];
    const float* w_ih0 = (const float*)d_in[1];
    const float* w_hh0 = (const float*)d_in[2];
    const float* b_ih0 = (const float*)d_in[3];
    const float* b_hh0 = (const float*)d_in[4];
    const float* w_ih1 = (const float*)d_in[5];
    const float* w_hh1 = (const float*)d_in[6];
    const float* b_ih1 = (const float*)d_in[7];
    const float* b_hh1 = (const float*)d_in[8];
    const float* fc_w  = (const float*)d_in[9];
    const float* fc_b  = (const float*)d_in[10];
    float* out = (float*)d_out;

    cudaFuncSetAttribute(lstm_layer_kernel<0>,
                         cudaFuncAttributeMaxDynamicSharedMemorySize, LSTM_SMEM);
    cudaFuncSetAttribute(lstm_layer_kernel<1>,
                         cudaFuncAttributeMaxDynamicSharedMemorySize, LSTM_SMEM);
    cudaFuncSetAttribute(xgate1_kernel,
                         cudaFuncAttributeMaxDynamicSharedMemorySize, XG_SMEM);

    prep_kernel<<<768, 256>>>(w_hh0, w_hh1, w_ih1);
    lstm_layer_kernel<0><<<BB / 2, 512, LSTM_SMEM>>>(x, w_ih0, b_ih0, b_hh0);
    xgate1_kernel<<<(BB * TT) / TRG, 512, XG_SMEM>>>(b_ih1, b_hh1);
    lstm_layer_kernel<1><<<BB / 2, 512, LSTM_SMEM>>>(nullptr, nullptr, nullptr, nullptr);
    fc_kernel<<<1, 256>>>(fc_w, fc_b, out);
}

// round 3
// speedup vs baseline: 1.0990x; 1.0990x over previous
#include <cuda_runtime.h>
#include <cuda_fp16.h>

#define BB   256
#define TT   512
#define HH   128
#define G4   512
#define IND  10
#define TRG  32

typedef unsigned long long u64;

// ---------------- packed f32x2 helpers ----------------
__device__ __forceinline__ void ffma2(u64& acc, u64 a, u64 b) {
    asm("fma.rn.f32x2 %0, %1, %2, %0;" : "+l"(acc) : "l"(a), "l"(b));
}
__device__ __forceinline__ u64 pk(float lo, float hi) {
    u64 d; asm("mov.b64 %0, {%1, %2};" : "=l"(d) : "f"(lo), "f"(hi)); return d;
}
__device__ __forceinline__ float psum(u64 a) {
    float x, y; asm("mov.b64 {%0, %1}, %2;" : "=f"(x), "=f"(y) : "l"(a));
    return x + y;
}
__device__ __forceinline__ u64 h2u64(unsigned int h2bits) {
    __half2 h = *reinterpret_cast<__half2*>(&h2bits);
    float2 f = __half22float2(h);
    u64 d; asm("mov.b64 %0, {%1, %2};" : "=l"(d) : "f"(f.x), "f"(f.y)); return d;
}

// ---------------- device-global scratch ----------------
__device__ __half g_whh0h[G4 * HH];
__device__ __half g_whh1h[G4 * HH];
__device__ __half g_wih1h[G4 * HH];
__device__ float  g_h1[(size_t)BB * TT * HH];
__device__ float  g_xg1[(size_t)BB * TT * G4];
__device__ float  g_h2last[BB * HH];

// Blocked fp16 layout: dst[(k>>3)*4096 + g*8 + (k&7)] = w[g*128 + k].
__global__ void prep_kernel(const float* __restrict__ w_hh0,
                            const float* __restrict__ w_hh1,
                            const float* __restrict__ w_ih1)
{
    int idx = blockIdx.x * blockDim.x + threadIdx.x;
    if (idx >= 3 * G4 * HH) return;
    int m = idx >> 16;
    int e = idx & 65535;
    int g = e >> 7;
    int k = e & 127;
    int dst = ((k >> 3) << 12) + (g << 3) + (k & 7);
    const float* s = (m == 0) ? w_hh0 : (m == 1 ? w_hh1 : w_ih1);
    __half*      d = (m == 0) ? g_whh0h : (m == 1 ? g_whh1h : g_wih1h);
    d[dst] = __float2half(s[e]);
}

__device__ __forceinline__ float sigf(float x) {
    return 1.0f / (1.0f + __expf(-x));
}
__device__ __forceinline__ float tanhfast(float x) {
    return 2.0f / (1.0f + __expf(-2.0f * x)) - 1.0f;
}

// ---------------- LSTM recurrence ----------------
// 128 CTAs x 2 batch rows, 512 threads; thread g computes gate g for both rows.
// k in [0,64):   fp32 weights held in 32 x 64-bit registers (exact)
// k in [64,128): fp16 weights in smem (blocked), F2F converted per step
// smem (bytes):
//   [0,65536)        w_hh fp16 blocked, k-blocks 8..15
//   [65536,86016)    w_ih0 fp32 k-major [10][512]   (layer0 only)
//   [86016,88064)    bias [512]                     (layer0 only)
//   [88064,89088)    hs [2][128]
//   [89088,93184)    gs [2][512]
//   [93184,93312)    xs [2][16]                     (layer0 only)
#define LSTM_SMEM 93312

template<int LAYER>
__global__ void __launch_bounds__(512, 1) lstm_layer_kernel(
    const float* __restrict__ x,
    const float* __restrict__ w_ih,
    const float* __restrict__ w_hh,
    const float* __restrict__ b_ih,
    const float* __restrict__ b_hh)
{
    extern __shared__ char smem[];
    __half* wsm    = (__half*)smem;
    float*  wih_s  = (float*)(smem + 65536);
    float*  bias_s = (float*)(smem + 86016);
    float*  hs     = (float*)(smem + 88064);
    float*  gs     = (float*)(smem + 89088);
    float*  xs     = (float*)(smem + 93184);

    const int tid = threadIdx.x;
    const int bb  = blockIdx.x;

    // fp32 weights for k<64 into registers (packed pairs)
    u64 wreg[32];
    {
        const u64* wg = (const u64*)(w_hh + (size_t)tid * HH);
        #pragma unroll
        for (int i = 0; i < 32; i++) wreg[i] = wg[i];
    }

    // fp16 weights for k in [64,128) into smem (blocks 8..15 of blocked layout)
    uint4*       wsm4 = (uint4*)wsm;
    const uint4* gw4  = (const uint4*)((LAYER == 0) ? g_whh0h : g_whh1h);
    #pragma unroll
    for (int i = 0; i < 8; i++)
        wsm4[i * 512 + tid] = gw4[(i + 8) * 512 + tid];

    if (LAYER == 0) {
        for (int i = tid; i < G4 * IND; i += 512) {
            int g = i / IND, j = i - g * IND;
            wih_s[j * 512 + g] = w_ih[i];
        }
        bias_s[tid] = b_ih[tid] + b_hh[tid];
    }
    if (tid < 256) hs[tid] = 0.0f;

    float creg = 0.0f;
    const int r_act = tid >> 7;
    const int j_act = tid & 127;

    // prefetch t=0 inputs
    float xg0 = 0.0f, xg1v = 0.0f;
    int xr = 0, xj = 0;
    if (LAYER == 0) {
        if (tid < 2 * IND) {
            xr = tid / IND; xj = tid - xr * IND;
            xs[xr * 16 + xj] = x[(size_t)(2 * bb + xr) * (TT * IND) + xj];
        }
    } else {
        xg0  = g_xg1[((size_t)(2 * bb + 0) * TT + 0) * G4 + tid];
        xg1v = g_xg1[((size_t)(2 * bb + 1) * TT + 0) * G4 + tid];
    }
    __syncthreads();

    const ulonglong2* h0v = (const ulonglong2*)hs;          // 16B = 2 packed pairs
    const ulonglong2* h1v = (const ulonglong2*)(hs + 128);

    for (int t = 0; t < TT; t++) {
        // [A] prefetch next step's inputs
        float nx = 0.0f, nxg0 = 0.0f, nxg1 = 0.0f;
        if (LAYER == 0) {
            if (tid < 2 * IND && t + 1 < TT)
                nx = x[(size_t)(2 * bb + xr) * (TT * IND) + (size_t)(t + 1) * IND + xj];
        } else {
            if (t + 1 < TT) {
                nxg0 = g_xg1[((size_t)(2 * bb + 0) * TT + (t + 1)) * G4 + tid];
                nxg1 = g_xg1[((size_t)(2 * bb + 1) * TT + (t + 1)) * G4 + tid];
            }
        }

        // [B] initial scalar part (bias + x-projection for layer0)
        float i0, i1;
        if (LAYER == 0) {
            float bv = bias_s[tid];
            i0 = bv; i1 = bv;
            #pragma unroll
            for (int j = 0; j < IND; j++) {
                float wv = wih_s[j * 512 + tid];
                i0 = fmaf(xs[j],      wv, i0);
                i1 = fmaf(xs[16 + j], wv, i1);
            }
        } else {
            i0 = xg0; i1 = xg1v;
        }

        u64 a0a = pk(i0, 0.0f), a0b = pk(0.0f, 0.0f);
        u64 a1a = pk(i1, 0.0f), a1b = pk(0.0f, 0.0f);

        // k in [0,64): fp32 register weights
        #pragma unroll
        for (int i = 0; i < 16; i++) {
            ulonglong2 h0 = h0v[i];
            ulonglong2 h1 = h1v[i];
            ffma2(a0a, h0.x, wreg[2 * i]);
            ffma2(a0b, h0.y, wreg[2 * i + 1]);
            ffma2(a1a, h1.x, wreg[2 * i]);
            ffma2(a1b, h1.y, wreg[2 * i + 1]);
        }

        // k in [64,128): fp16 smem weights
        #pragma unroll
        for (int c = 0; c < 8; c++) {
            uint4 wp = wsm4[c * 512 + tid];
            u64 w0 = h2u64(wp.x);
            u64 w1 = h2u64(wp.y);
            u64 w2 = h2u64(wp.z);
            u64 w3 = h2u64(wp.w);
            ulonglong2 ha = h0v[16 + 2 * c];
            ulonglong2 hb = h0v[16 + 2 * c + 1];
            ulonglong2 ka = h1v[16 + 2 * c];
            ulonglong2 kb = h1v[16 + 2 * c + 1];
            ffma2(a0a, ha.x, w0); ffma2(a0b, ha.y, w1);
            ffma2(a0a, hb.x, w2); ffma2(a0b, hb.y, w3);
            ffma2(a1a, ka.x, w0); ffma2(a1b, ka.y, w1);
            ffma2(a1a, kb.x, w2); ffma2(a1b, kb.y, w3);
        }

        gs[tid]       = psum(a0a) + psum(a0b);
        gs[512 + tid] = psum(a1a) + psum(a1b);
        __syncthreads();

        // [C] activations + state update
        if (tid < 256) {
            const float* gr = gs + r_act * 512;
            float iv = sigf(gr[j_act]);
            float fv = sigf(gr[128 + j_act]);
            float gv = tanhfast(gr[256 + j_act]);
            float ov = sigf(gr[384 + j_act]);
            creg = fv * creg + iv * gv;
            float hn = ov * tanhfast(creg);
            hs[r_act * 128 + j_act] = hn;
            if (LAYER == 0) {
                g_h1[((size_t)(2 * bb + r_act) * TT + t) * HH + j_act] = hn;
            } else if (t == TT - 1) {
                g_h2last[(2 * bb + r_act) * HH + j_act] = hn;
            }
        }
        if (LAYER == 0) {
            if (tid < 2 * IND) xs[xr * 16 + xj] = nx;
        } else {
            xg0 = nxg0; xg1v = nxg1;
        }
        __syncthreads();
    }
}

// ---------------- layer-1 input projection GEMM (FFMA2) ----------------
#define XG_SMEM (131072 + TRG * HH * 4)

__global__ void __launch_bounds__(512, 1) xgate1_kernel(
    const float* __restrict__ b_ih1, const float* __restrict__ b_hh1)
{
    extern __shared__ char smem[];
    __half* wsm = (__half*)smem;
    float*  h_s = (float*)(smem + 131072);

    const int tid = threadIdx.x;

    uint4*       wsm4 = (uint4*)wsm;
    const uint4* gw4  = (const uint4*)g_wih1h;
    #pragma unroll
    for (int i = 0; i < 16; i++)
        wsm4[i * 512 + tid] = gw4[i * 512 + tid];

    const size_t base = (size_t)blockIdx.x * TRG * HH;
    float4*       h_s4 = (float4*)h_s;
    const float4* src4 = (const float4*)(g_h1 + base);
    #pragma unroll
    for (int i = 0; i < (TRG * HH / 4) / 512; i++)
        h_s4[i * 512 + tid] = src4[i * 512 + tid];
    __syncthreads();

    float bv = b_ih1[tid] + b_hh1[tid];
    u64 acc[TRG];
    #pragma unroll
    for (int r = 0; r < TRG; r++) acc[r] = pk(bv, 0.0f);

    #pragma unroll 1
    for (int c = 0; c < 16; c++) {
        uint4 wp = wsm4[c * 512 + tid];
        u64 w0 = h2u64(wp.x);
        u64 w1 = h2u64(wp.y);
        u64 w2 = h2u64(wp.z);
        u64 w3 = h2u64(wp.w);
        #pragma unroll
        for (int r = 0; r < TRG; r++) {
            ulonglong2 ha = *(const ulonglong2*)(h_s + r * HH + c * 8);
            ulonglong2 hb = *(const ulonglong2*)(h_s + r * HH + c * 8 + 4);
            ffma2(acc[r], ha.x, w0);
            ffma2(acc[r], ha.y, w1);
            ffma2(acc[r], hb.x, w2);
            ffma2(acc[r], hb.y, w3);
        }
    }

    #pragma unroll
    for (int r = 0; r < TRG; r++)
        g_xg1[((size_t)blockIdx.x * TRG + r) * G4 + tid] = psum(acc[r]);
}

// ---------------- final FC ----------------
__global__ void fc_kernel(const float* __restrict__ fc_w,
                          const float* __restrict__ fc_b,
                          float* __restrict__ out)
{
    int b = threadIdx.x;
    const float* hrow = g_h2last + b * HH;
    #pragma unroll
    for (int c = 0; c < 10; c++) {
        float acc = fc_b[c];
        #pragma unroll
        for (int k = 0; k < HH; k++)
            acc = fmaf(hrow[k], fc_w[c * HH + k], acc);
        out[b * 10 + c] = acc;
    }
}

extern "C" void kernel_launch(void* const* d_in, const int* in_sizes, int n_in,
                              void* d_out, int out_size)
{
    const float* x     = (const float*)d_in[0];
    const float* w_ih0 = (const float*)d_in[1];
    const float* w_hh0 = (const float*)d_in[2];
    const float* b_ih0 = (const float*)d_in[3];
    const float* b_hh0 = (const float*)d_in[4];
    const float* w_ih1 = (const float*)d_in[5];
    const float* w_hh1 = (const float*)d_in[6];
    const float* b_ih1 = (const float*)d_in[7];
    const float* b_hh1 = (const float*)d_in[8];
    const float* fc_w  = (const float*)d_in[9];
    const float* fc_b  = (const float*)d_in[10];
    float* out = (float*)d_out;

    cudaFuncSetAttribute(lstm_layer_kernel<0>,
                         cudaFuncAttributeMaxDynamicSharedMemorySize, LSTM_SMEM);
    cudaFuncSetAttribute(lstm_layer_kernel<1>,
                         cudaFuncAttributeMaxDynamicSharedMemorySize, LSTM_SMEM);
    cudaFuncSetAttribute(xgate1_kernel,
                         cudaFuncAttributeMaxDynamicSharedMemorySize, XG_SMEM);

    prep_kernel<<<768, 256>>>(w_hh0, w_hh1, w_ih1);
    lstm_layer_kernel<0><<<BB / 2, 512, LSTM_SMEM>>>(x, w_ih0, w_hh0, b_ih0, b_hh0);
    xgate1_kernel<<<(BB * TT) / TRG, 512, XG_SMEM>>>(b_ih1, b_hh1);
    lstm_layer_kernel<1><<<BB / 2, 512, LSTM_SMEM>>>(nullptr, nullptr, w_hh1, nullptr, nullptr);
    fc_kernel<<<1, 256>>>(fc_w, fc_b, out);
}

// round 4
// speedup vs baseline: 1.3344x; 1.2143x over previous
#include <cuda_runtime.h>
#include <cuda_fp16.h>

#define BB   256
#define TT   512
#define HH   128
#define G4   512
#define IND  10
#define TRG  32

typedef unsigned long long u64;

// ---------------- packed f32x2 helpers ----------------
__device__ __forceinline__ void ffma2(u64& acc, u64 a, u64 b) {
    asm("fma.rn.f32x2 %0, %1, %2, %0;" : "+l"(acc) : "l"(a), "l"(b));
}
__device__ __forceinline__ u64 pk(float lo, float hi) {
    u64 d; asm("mov.b64 %0, {%1, %2};" : "=l"(d) : "f"(lo), "f"(hi)); return d;
}
__device__ __forceinline__ float psum(u64 a) {
    float x, y; asm("mov.b64 {%0, %1}, %2;" : "=f"(x), "=f"(y) : "l"(a));
    return x + y;
}
__device__ __forceinline__ u64 h2u64(unsigned int h2bits) {
    __half2 h = *reinterpret_cast<__half2*>(&h2bits);
    float2 f = __half22float2(h);
    u64 d; asm("mov.b64 %0, {%1, %2};" : "=l"(d) : "f"(f.x), "f"(f.y)); return d;
}

// ---------------- device-global scratch ----------------
__device__ __half g_whh0h[G4 * HH];
__device__ __half g_whh1h[G4 * HH];
__device__ __half g_wih1h[G4 * HH];
__device__ float  g_h1[(size_t)BB * TT * HH];
__device__ float  g_xg1[(size_t)BB * TT * G4];
__device__ float  g_h2last[BB * HH];

// Blocked fp16 layout: dst[(k>>3)*4096 + g*8 + (k&7)] = w[g*128 + k].
__global__ void prep_kernel(const float* __restrict__ w_hh0,
                            const float* __restrict__ w_hh1,
                            const float* __restrict__ w_ih1)
{
    int idx = blockIdx.x * blockDim.x + threadIdx.x;
    if (idx >= 3 * G4 * HH) return;
    int m = idx >> 16;
    int e = idx & 65535;
    int g = e >> 7;
    int k = e & 127;
    int dst = ((k >> 3) << 12) + (g << 3) + (k & 7);
    const float* s = (m == 0) ? w_hh0 : (m == 1 ? w_hh1 : w_ih1);
    __half*      d = (m == 0) ? g_whh0h : (m == 1 ? g_whh1h : g_wih1h);
    d[dst] = __float2half(s[e]);
}

__device__ __forceinline__ float sigf(float x) {
    return 1.0f / (1.0f + __expf(-x));
}
__device__ __forceinline__ float tanhfast(float x) {
    return 2.0f / (1.0f + __expf(-2.0f * x)) - 1.0f;
}

// ---------------- LSTM recurrence ----------------
// 128 CTAs x 2 batch rows, 256 threads; thread computes gates {tid, tid+256}
// for both rows. k<64: fp32 weights in registers (both gates, exact, no LDS).
// k in [64,128): fp16 weights in smem (blocked layout blocks 8..15).
// smem (bytes):
//   [0,65536)        w_hh fp16 blocked, k-blocks 8..15
//   [65536,86016)    w_ih0 fp32 k-major [10][512]   (layer0 only)
//   [86016,88064)    bias [512]                     (layer0 only)
//   [88064,89088)    hs [2][128]
//   [89088,93184)    gs [2][512]
//   [93184,93312)    xs [2][16]                     (layer0 only)
#define LSTM_SMEM 93312

template<int LAYER>
__global__ void __launch_bounds__(256, 1) lstm_layer_kernel(
    const float* __restrict__ x,
    const float* __restrict__ w_ih,
    const float* __restrict__ w_hh,
    const float* __restrict__ b_ih,
    const float* __restrict__ b_hh)
{
    extern __shared__ char smem[];
    __half* wsm    = (__half*)smem;
    float*  wih_s  = (float*)(smem + 65536);
    float*  bias_s = (float*)(smem + 86016);
    float*  hs     = (float*)(smem + 88064);
    float*  gs     = (float*)(smem + 89088);
    float*  xs     = (float*)(smem + 93184);

    const int tid = threadIdx.x;
    const int bb  = blockIdx.x;
    const int g0  = tid;
    const int g1  = tid + 256;

    // fp32 weights for k<64, both gates, into registers (packed pairs)
    u64 wreg0[32], wreg1[32];
    {
        const u64* wa = (const u64*)(w_hh + (size_t)g0 * HH);
        const u64* wb = (const u64*)(w_hh + (size_t)g1 * HH);
        #pragma unroll
        for (int i = 0; i < 32; i++) { wreg0[i] = wa[i]; wreg1[i] = wb[i]; }
    }

    // fp16 weights for k in [64,128) into smem (blocks 8..15 of blocked layout)
    uint4*       wsm4 = (uint4*)wsm;
    const uint4* gw4  = (const uint4*)((LAYER == 0) ? g_whh0h : g_whh1h);
    #pragma unroll
    for (int i = 0; i < 8; i++) {
        wsm4[i * 512 + g0] = gw4[(i + 8) * 512 + g0];
        wsm4[i * 512 + g1] = gw4[(i + 8) * 512 + g1];
    }

    if (LAYER == 0) {
        for (int i = tid; i < G4 * IND; i += 256) {
            int g = i / IND, j = i - g * IND;
            wih_s[j * 512 + g] = w_ih[i];
        }
        bias_s[g0] = b_ih[g0] + b_hh[g0];
        bias_s[g1] = b_ih[g1] + b_hh[g1];
    }
    hs[tid] = 0.0f;

    float creg = 0.0f;                 // cell state: thread = (row, unit)
    const int r_act = tid >> 7;
    const int j_act = tid & 127;

    // prefetch t=0 step inputs
    float xg00 = 0.0f, xg01 = 0.0f, xg10 = 0.0f, xg11 = 0.0f; // [row][gate]
    int xr = 0, xj = 0;
    if (LAYER == 0) {
        if (tid < 2 * IND) {
            xr = tid / IND; xj = tid - xr * IND;
            xs[xr * 16 + xj] = x[(size_t)(2 * bb + xr) * (TT * IND) + xj];
        }
    } else {
        const float* p0 = g_xg1 + ((size_t)(2 * bb + 0) * TT + 0) * G4;
        const float* p1 = g_xg1 + ((size_t)(2 * bb + 1) * TT + 0) * G4;
        xg00 = p0[g0]; xg01 = p0[g1];
        xg10 = p1[g0]; xg11 = p1[g1];
    }
    __syncthreads();

    const ulonglong2* h0v = (const ulonglong2*)hs;          // 16B = 4 floats
    const ulonglong2* h1v = (const ulonglong2*)(hs + 128);

    for (int t = 0; t < TT; t++) {
        // [A] prefetch next step's inputs
        float nx = 0.0f, n00 = 0.0f, n01 = 0.0f, n10 = 0.0f, n11 = 0.0f;
        if (LAYER == 0) {
            if (tid < 2 * IND && t + 1 < TT)
                nx = x[(size_t)(2 * bb + xr) * (TT * IND) + (size_t)(t + 1) * IND + xj];
        } else {
            if (t + 1 < TT) {
                const float* p0 = g_xg1 + ((size_t)(2 * bb + 0) * TT + (t + 1)) * G4;
                const float* p1 = g_xg1 + ((size_t)(2 * bb + 1) * TT + (t + 1)) * G4;
                n00 = p0[g0]; n01 = p0[g1];
                n10 = p1[g0]; n11 = p1[g1];
            }
        }

        // [B] initial scalar part (bias + x-projection for layer0)
        float i00, i01, i10, i11;                    // [row][gate]
        if (LAYER == 0) {
            float bv0 = bias_s[g0], bv1 = bias_s[g1];
            i00 = bv0; i01 = bv1; i10 = bv0; i11 = bv1;
            #pragma unroll
            for (int j = 0; j < IND; j++) {
                float w0 = wih_s[j * 512 + g0];
                float w1 = wih_s[j * 512 + g1];
                float x0 = xs[j], x1 = xs[16 + j];
                i00 = fmaf(x0, w0, i00);
                i01 = fmaf(x0, w1, i01);
                i10 = fmaf(x1, w0, i10);
                i11 = fmaf(x1, w1, i11);
            }
        } else {
            i00 = xg00; i01 = xg01; i10 = xg10; i11 = xg11;
        }

        // accumulators: [gate][row][split]
        u64 a00a = pk(i00, 0.0f), a00b = pk(0.0f, 0.0f);
        u64 a01a = pk(i10, 0.0f), a01b = pk(0.0f, 0.0f);
        u64 a10a = pk(i01, 0.0f), a10b = pk(0.0f, 0.0f);
        u64 a11a = pk(i11, 0.0f), a11b = pk(0.0f, 0.0f);

        // k in [0,64): fp32 register weights, both gates
        #pragma unroll
        for (int i = 0; i < 16; i++) {
            ulonglong2 h0 = h0v[i];
            ulonglong2 h1 = h1v[i];
            ffma2(a00a, h0.x, wreg0[2 * i]);
            ffma2(a00b, h0.y, wreg0[2 * i + 1]);
            ffma2(a01a, h1.x, wreg0[2 * i]);
            ffma2(a01b, h1.y, wreg0[2 * i + 1]);
            ffma2(a10a, h0.x, wreg1[2 * i]);
            ffma2(a10b, h0.y, wreg1[2 * i + 1]);
            ffma2(a11a, h1.x, wreg1[2 * i]);
            ffma2(a11b, h1.y, wreg1[2 * i + 1]);
        }

        // k in [64,128): fp16 smem weights, both gates
        #pragma unroll
        for (int c = 0; c < 8; c++) {
            uint4 wpA = wsm4[c * 512 + g0];
            uint4 wpB = wsm4[c * 512 + g1];
            u64 wA0 = h2u64(wpA.x), wA1 = h2u64(wpA.y);
            u64 wA2 = h2u64(wpA.z), wA3 = h2u64(wpA.w);
            u64 wB0 = h2u64(wpB.x), wB1 = h2u64(wpB.y);
            u64 wB2 = h2u64(wpB.z), wB3 = h2u64(wpB.w);
            ulonglong2 ha = h0v[16 + 2 * c];
            ulonglong2 hb = h0v[16 + 2 * c + 1];
            ulonglong2 ka = h1v[16 + 2 * c];
            ulonglong2 kb = h1v[16 + 2 * c + 1];
            ffma2(a00a, ha.x, wA0); ffma2(a00b, ha.y, wA1);
            ffma2(a00a, hb.x, wA2); ffma2(a00b, hb.y, wA3);
            ffma2(a01a, ka.x, wA0); ffma2(a01b, ka.y, wA1);
            ffma2(a01a, kb.x, wA2); ffma2(a01b, kb.y, wA3);
            ffma2(a10a, ha.x, wB0); ffma2(a10b, ha.y, wB1);
            ffma2(a10a, hb.x, wB2); ffma2(a10b, hb.y, wB3);
            ffma2(a11a, ka.x, wB0); ffma2(a11b, ka.y, wB1);
            ffma2(a11a, kb.x, wB2); ffma2(a11b, kb.y, wB3);
        }

        gs[g0]       = psum(a00a) + psum(a00b);
        gs[g1]       = psum(a10a) + psum(a10b);
        gs[512 + g0] = psum(a01a) + psum(a01b);
        gs[512 + g1] = psum(a11a) + psum(a11b);
        __syncthreads();

        // [C] activations + state update (all 256 threads; one (row,unit) each)
        {
            const float* gr = gs + r_act * 512;
            float iv = sigf(gr[j_act]);
            float fv = sigf(gr[128 + j_act]);
            float gv = tanhfast(gr[256 + j_act]);
            float ov = sigf(gr[384 + j_act]);
            creg = fv * creg + iv * gv;
            float hn = ov * tanhfast(creg);
            hs[r_act * 128 + j_act] = hn;
            if (LAYER == 0) {
                g_h1[((size_t)(2 * bb + r_act) * TT + t) * HH + j_act] = hn;
            } else if (t == TT - 1) {
                g_h2last[(2 * bb + r_act) * HH + j_act] = hn;
            }
        }
        if (LAYER == 0) {
            if (tid < 2 * IND) xs[xr * 16 + xj] = nx;
        } else {
            xg00 = n00; xg01 = n01; xg10 = n10; xg11 = n11;
        }
        __syncthreads();
    }
}

// ---------------- layer-1 input projection GEMM (FFMA2) ----------------
#define XG_SMEM (131072 + TRG * HH * 4)

__global__ void __launch_bounds__(512, 1) xgate1_kernel(
    const float* __restrict__ b_ih1, const float* __restrict__ b_hh1)
{
    extern __shared__ char smem[];
    __half* wsm = (__half*)smem;
    float*  h_s = (float*)(smem + 131072);

    const int tid = threadIdx.x;

    uint4*       wsm4 = (uint4*)wsm;
    const uint4* gw4  = (const uint4*)g_wih1h;
    #pragma unroll
    for (int i = 0; i < 16; i++)
        wsm4[i * 512 + tid] = gw4[i * 512 + tid];

    const size_t base = (size_t)blockIdx.x * TRG * HH;
    float4*       h_s4 = (float4*)h_s;
    const float4* src4 = (const float4*)(g_h1 + base);
    #pragma unroll
    for (int i = 0; i < (TRG * HH / 4) / 512; i++)
        h_s4[i * 512 + tid] = src4[i * 512 + tid];
    __syncthreads();

    float bv = b_ih1[tid] + b_hh1[tid];
    u64 acc[TRG];
    #pragma unroll
    for (int r = 0; r < TRG; r++) acc[r] = pk(bv, 0.0f);

    #pragma unroll 1
    for (int c = 0; c < 16; c++) {
        uint4 wp = wsm4[c * 512 + tid];
        u64 w0 = h2u64(wp.x);
        u64 w1 = h2u64(wp.y);
        u64 w2 = h2u64(wp.z);
        u64 w3 = h2u64(wp.w);
        #pragma unroll
        for (int r = 0; r < TRG; r++) {
            ulonglong2 ha = *(const ulonglong2*)(h_s + r * HH + c * 8);
            ulonglong2 hb = *(const ulonglong2*)(h_s + r * HH + c * 8 + 4);
            ffma2(acc[r], ha.x, w0);
            ffma2(acc[r], ha.y, w1);
            ffma2(acc[r], hb.x, w2);
            ffma2(acc[r], hb.y, w3);
        }
    }

    #pragma unroll
    for (int r = 0; r < TRG; r++)
        g_xg1[((size_t)blockIdx.x * TRG + r) * G4 + tid] = psum(acc[r]);
}

// ---------------- final FC ----------------
__global__ void fc_kernel(const float* __restrict__ fc_w,
                          const float* __restrict__ fc_b,
                          float* __restrict__ out)
{
    int b = threadIdx.x;
    const float* hrow = g_h2last + b * HH;
    #pragma unroll
    for (int c = 0; c < 10; c++) {
        float acc = fc_b[c];
        #pragma unroll
        for (int k = 0; k < HH; k++)
            acc = fmaf(hrow[k], fc_w[c * HH + k], acc);
        out[b * 10 + c] = acc;
    }
}

extern "C" void kernel_launch(void* const* d_in, const int* in_sizes, int n_in,
                              void* d_out, int out_size)
{
    const float* x     = (const float*)d_in[0];
    const float* w_ih0 = (const float*)d_in[1];
    const float* w_hh0 = (const float*)d_in[2];
    const float* b_ih0 = (const float*)d_in[3];
    const float* b_hh0 = (const float*)d_in[4];
    const float* w_ih1 = (const float*)d_in[5];
    const float* w_hh1 = (const float*)d_in[6];
    const float* b_ih1 = (const float*)d_in[7];
    const float* b_hh1 = (const float*)d_in[8];
    const float* fc_w  = (const float*)d_in[9];
    const float* fc_b  = (const float*)d_in[10];
    float* out = (float*)d_out;

    cudaFuncSetAttribute(lstm_layer_kernel<0>,
                         cudaFuncAttributeMaxDynamicSharedMemorySize, LSTM_SMEM);
    cudaFuncSetAttribute(lstm_layer_kernel<1>,
                         cudaFuncAttributeMaxDynamicSharedMemorySize, LSTM_SMEM);
    cudaFuncSetAttribute(xgate1_kernel,
                         cudaFuncAttributeMaxDynamicSharedMemorySize, XG_SMEM);

    prep_kernel<<<768, 256>>>(w_hh0, w_hh1, w_ih1);
    lstm_layer_kernel<0><<<BB / 2, 256, LSTM_SMEM>>>(x, w_ih0, w_hh0, b_ih0, b_hh0);
    xgate1_kernel<<<(BB * TT) / TRG, 512, XG_SMEM>>>(b_ih1, b_hh1);
    lstm_layer_kernel<1><<<BB / 2, 256, LSTM_SMEM>>>(nullptr, nullptr, w_hh1, nullptr, nullptr);
    fc_kernel<<<1, 256>>>(fc_w, fc_b, out);
}